// round 13
// baseline (speedup 1.0000x reference)
#include <cuda_runtime.h>
#include <cstdint>

#define N_BITS 108
#define N_OUT  7
#define TPB    256

// Row = 108 floats = 432 B = 27 uint4. Values exactly 0.0f/1.0f:
// (word >> 29) & 1 extracts the bit.
//
// R11 analysis: warp-level early exit is illusory — P(warp has an unresolved
// lane after k rounds) ~ 1 for k<=2 — so every warp ran the full 4-deep
// dependent ladder while measured traffic (~265 B/row) already equals a
// 2-stage schedule's cost. So: TWO dependent stages only.
//   Stage 0: words 0..7   (128 B, 8 independent LDG.128)  -> 62% of lanes
//   Stage 1: words 8..26  (304 B, 19 independent LDG.128) -> lane-predicated
// Same bytes, half the chain depth.

__device__ __forceinline__ unsigned mask4(uint4 w) {
    return ((w.x >> 29) & 1u)
         | (((w.y >> 29) & 1u) << 1)
         | (((w.z >> 29) & 1u) << 2)
         | (((w.w >> 29) & 1u) << 3);
}

__global__ __launch_bounds__(TPB, 8)
void lzd108_kernel(const uint4* __restrict__ X, float* __restrict__ out, int n_rows) {
    __shared__ unsigned short s_pos[TPB];

    int tid = threadIdx.x;
    size_t brow = (size_t)blockIdx.x * TPB;
    int row = (int)brow + tid;
    int pos = N_BITS;  // 108 = 1101100b == LZC_108 (all-zero row)

    if (row < n_rows) {
        const uint4* p = X + (size_t)row * 27;

        // Stage 0: bits [0,32) — words 0..7, one 128 B batch
        unsigned m = 0;
        #pragma unroll
        for (int j = 0; j < 8; ++j) m |= mask4(__ldg(p + j)) << (4 * j);
        if (m) {
            pos = __ffs(m) - 1;
        } else {
            // Stage 1: bits [32,108) — words 8..26, one 304 B batch of
            // 19 mutually independent loads (streams after first consume).
            unsigned long long mlo = 0;
            #pragma unroll
            for (int j = 0; j < 16; ++j)
                mlo |= (unsigned long long)mask4(__ldg(p + 8 + j)) << (4 * j);
            unsigned mhi = 0;
            #pragma unroll
            for (int j = 0; j < 3; ++j)
                mhi |= mask4(__ldg(p + 24 + j)) << (4 * j);

            if (mlo)      pos = 32 + __ffsll(mlo) - 1;
            else if (mhi) pos = 96 + __ffs(mhi) - 1;
            // else stays 108
        }
    }

    s_pos[tid] = (unsigned short)pos;
    __syncthreads();

    // Coalesced output: block writes its 1792 floats contiguously,
    // reconstructing bits from s_pos.
    size_t ob = brow * N_OUT;
    size_t total = (size_t)n_rows * N_OUT;
    #pragma unroll
    for (int i = 0; i < N_OUT; ++i) {
        size_t gi = ob + (size_t)(i * TPB + tid);
        if (gi < total) {
            int local = i * TPB + tid;   // 0..1791
            int r = local / N_OUT;
            int b = local - r * N_OUT;
            out[gi] = (float)((s_pos[r] >> (6 - b)) & 1);
        }
    }
}

extern "C" void kernel_launch(void* const* d_in, const int* in_sizes, int n_in,
                              void* d_out, int out_size) {
    const uint4* X = (const uint4*)d_in[0];
    float* out = (float*)d_out;
    int n_rows = in_sizes[0] / N_BITS;

    int blocks = (n_rows + TPB - 1) / TPB;
    lzd108_kernel<<<blocks, TPB>>>(X, out, n_rows);
}